// round 8
// baseline (speedup 1.0000x reference)
#include <cuda_runtime.h>

#define Bn 2
#define H 384
#define W 1280
#define HW (H * W)
#define BHW (Bn * H * W)

// Persistent scratch (no allocations allowed in kernel_launch).
__device__ float g_w[8 * BHW];   // normalized, mask-folded weights, plane-major [k][b][i][j]
__device__ float g_c[BHW];       // constant term per pixel
__device__ float g_d0[BHW];      // ping
__device__ float g_d1[BHW];      // pong

// Neighbor offsets per channel k (derived from PADS):
// k0:(+1,+1) k1:(+1,0) k2:(+1,-1) k3:(0,+1) k4:(0,-1) k5:(-1,+1) k6:(-1,0) k7:(-1,-1)
__constant__ int c_di[8] = { 1, 1, 1, 0, 0, -1, -1, -1 };
__constant__ int c_dj[8] = { 1, 0, -1, 1, -1, 1, 0, -1 };

__global__ void prep_kernel(const float* __restrict__ guid,
                            const float* __restrict__ blur,
                            const float* __restrict__ sparse) {
    int idx = blockIdx.x * blockDim.x + threadIdx.x;
    if (idx >= BHW) return;
    int j = idx % W;
    int t = idx / W;
    int i = t % H;
    int b = t / H;

    float v[8];
    float den = 0.0f;
#pragma unroll
    for (int k = 0; k < 8; k++) {
        int ni = i + c_di[k];
        int nj = j + c_dj[k];
        float val = 0.0f;
        if (ni >= 0 && ni < H && nj >= 0 && nj < W)
            val = guid[((b * 8 + k) * H + ni) * W + nj];
        v[k] = val;
        den += fabsf(val);
    }
    float inv = 1.0f / (den + 1e-9f);
    float gs = 0.0f;
#pragma unroll
    for (int k = 0; k < 8; k++) {
        v[k] *= inv;
        gs += v[k];
    }
    float m = (sparse[idx] > 0.0f) ? 1.0f : 0.0f;
    float fac = 1.0f - m;
    float raw = blur[idx];
    g_c[idx] = (fac * (1.0f - gs) + m) * raw;
#pragma unroll
    for (int k = 0; k < 8; k++)
        g_w[k * BHW + idx] = fac * v[k];
}

// Load 6 consecutive d values [j0-1 .. j0+4] from one row (clamped at edges;
// the clamped values are always multiplied by an exactly-zero weight).
__device__ __forceinline__ void load_row6(const float* __restrict__ row, int j0, float v[6]) {
    v[0] = row[(j0 > 0) ? (j0 - 1) : 0];
    float4 mid = *reinterpret_cast<const float4*>(row + j0);
    v[1] = mid.x; v[2] = mid.y; v[3] = mid.z; v[4] = mid.w;
    v[5] = row[(j0 + 4 < W) ? (j0 + 4) : (W - 1)];
}

// One Jacobi sweep: d_new = C + sum_k w'_k * d[nbr_k].  4 pixels per thread.
__global__ __launch_bounds__(256) void prop_kernel(const float* __restrict__ src,
                                                   float* __restrict__ dst) {
    int j0 = (blockIdx.x * blockDim.x + threadIdx.x) * 4;   // W=1280 = 10 blocks * 32 lanes * 4
    int i  = blockIdx.y * blockDim.y + threadIdx.y;         // H=384  = 48 blocks * 8
    int b  = blockIdx.z;
    int base = (b * H + i) * W + j0;

    const float* plane = src + b * HW;
    int iu = (i > 0) ? (i - 1) : 0;
    int id = (i + 1 < H) ? (i + 1) : (H - 1);

    float ru[6], rm[6], rd[6];
    load_row6(plane + iu * W, j0, ru);
    load_row6(plane + i  * W, j0, rm);
    load_row6(plane + id * W, j0, rd);

    float4 c4 = *reinterpret_cast<const float4*>(g_c + base);
    float c[4] = { c4.x, c4.y, c4.z, c4.w };

    float wk[8][4];
#pragma unroll
    for (int k = 0; k < 8; k++) {
        float4 t = *reinterpret_cast<const float4*>(g_w + k * BHW + base);
        wk[k][0] = t.x; wk[k][1] = t.y; wk[k][2] = t.z; wk[k][3] = t.w;
    }

    float o[4];
#pragma unroll
    for (int p = 0; p < 4; p++) {
        float acc = c[p];
        acc = fmaf(wk[0][p], rd[p + 2], acc);   // (+1,+1)
        acc = fmaf(wk[1][p], rd[p + 1], acc);   // (+1, 0)
        acc = fmaf(wk[2][p], rd[p],     acc);   // (+1,-1)
        acc = fmaf(wk[3][p], rm[p + 2], acc);   // ( 0,+1)
        acc = fmaf(wk[4][p], rm[p],     acc);   // ( 0,-1)
        acc = fmaf(wk[5][p], ru[p + 2], acc);   // (-1,+1)
        acc = fmaf(wk[6][p], ru[p + 1], acc);   // (-1, 0)
        acc = fmaf(wk[7][p], ru[p],     acc);   // (-1,-1)
        o[p] = acc;
    }
    *reinterpret_cast<float4*>(dst + base) = make_float4(o[0], o[1], o[2], o[3]);
}

extern "C" void kernel_launch(void* const* d_in, const int* in_sizes, int n_in,
                              void* d_out, int out_size) {
    const float* guid   = (const float*)d_in[0];   // (B, 8, H, W)
    const float* blur   = (const float*)d_in[1];   // (B, 1, H, W)
    const float* sparse = (const float*)d_in[2];   // (B, 1, H, W)
    float* out = (float*)d_out;                    // (B, H, W)

    const int PROP_TIME = 24;                      // fixed by setup_inputs

    prep_kernel<<<(BHW + 255) / 256, 256>>>(guid, blur, sparse);

    float* dbuf[2];
    cudaGetSymbolAddress((void**)&dbuf[0], g_d0);
    cudaGetSymbolAddress((void**)&dbuf[1], g_d1);

    dim3 block(32, 8, 1);
    dim3 grid(W / (32 * 4), H / 8, Bn);            // (10, 48, 2)

    const float* src = blur;
    for (int t = 1; t <= PROP_TIME; t++) {
        float* dst = (t == PROP_TIME) ? out : dbuf[t & 1];
        prop_kernel<<<grid, block>>>(src, dst);
        src = dst;
    }
}

// round 9
// speedup vs baseline: 1.0187x; 1.0187x over previous
#include <cuda_runtime.h>

#define Bn 2
#define H 384
#define W 1280
#define HW (H * W)
#define BHW (Bn * H * W)

// Persistent scratch (no allocations allowed in kernel_launch).
__device__ float g_w[8 * BHW];   // normalized, mask-folded weights, plane-major [k][b][i][j]
__device__ float g_c[BHW];       // constant term per pixel
__device__ float g_d0[BHW];      // ping
__device__ float g_d1[BHW];      // pong

// Neighbor offsets per channel k (derived from PADS):
// k0:(+1,+1) k1:(+1,0) k2:(+1,-1) k3:(0,+1) k4:(0,-1) k5:(-1,+1) k6:(-1,0) k7:(-1,-1)
__constant__ int c_di[8] = { 1, 1, 1, 0, 0, -1, -1, -1 };
__constant__ int c_dj[8] = { 1, 0, -1, 1, -1, 1, 0, -1 };

__global__ void prep_kernel(const float* __restrict__ guid,
                            const float* __restrict__ blur,
                            const float* __restrict__ sparse) {
    int idx = blockIdx.x * blockDim.x + threadIdx.x;
    if (idx >= BHW) return;
    int j = idx % W;
    int t = idx / W;
    int i = t % H;
    int b = t / H;

    float v[8];
    float den = 0.0f;
#pragma unroll
    for (int k = 0; k < 8; k++) {
        int ni = i + c_di[k];
        int nj = j + c_dj[k];
        float val = 0.0f;
        if (ni >= 0 && ni < H && nj >= 0 && nj < W)
            val = guid[((b * 8 + k) * H + ni) * W + nj];
        v[k] = val;
        den += fabsf(val);
    }
    float inv = 1.0f / (den + 1e-9f);
    float gs = 0.0f;
#pragma unroll
    for (int k = 0; k < 8; k++) {
        v[k] *= inv;
        gs += v[k];
    }
    float m = (sparse[idx] > 0.0f) ? 1.0f : 0.0f;
    float fac = 1.0f - m;
    float raw = blur[idx];
    g_c[idx] = (fac * (1.0f - gs) + m) * raw;
#pragma unroll
    for (int k = 0; k < 8; k++)
        g_w[k * BHW + idx] = fac * v[k];
}

// Load 6 consecutive d values [j0-1 .. j0+4] from one row (clamped at edges;
// the clamped values are always multiplied by an exactly-zero weight).
__device__ __forceinline__ void load_row6(const float* __restrict__ row, int j0, float v[6]) {
    v[0] = row[(j0 > 0) ? (j0 - 1) : 0];
    float4 mid = *reinterpret_cast<const float4*>(row + j0);
    v[1] = mid.x; v[2] = mid.y; v[3] = mid.z; v[4] = mid.w;
    v[5] = row[(j0 + 4 < W) ? (j0 + 4) : (W - 1)];
}

// One Jacobi sweep: d_new = C + sum_k w'_k * d[nbr_k].  4 pixels per thread.
__global__ __launch_bounds__(256) void prop_kernel(const float* __restrict__ src,
                                                   float* __restrict__ dst) {
    int j0 = (blockIdx.x * blockDim.x + threadIdx.x) * 4;   // W=1280 = 10 blocks * 32 lanes * 4
    int i  = blockIdx.y * blockDim.y + threadIdx.y;         // H=384  = 48 blocks * 8
    int b  = blockIdx.z;
    int base = (b * H + i) * W + j0;

    const float* plane = src + b * HW;
    int iu = (i > 0) ? (i - 1) : 0;
    int id = (i + 1 < H) ? (i + 1) : (H - 1);

    float ru[6], rm[6], rd[6];
    load_row6(plane + iu * W, j0, ru);
    load_row6(plane + i  * W, j0, rm);
    load_row6(plane + id * W, j0, rd);

    float4 c4 = *reinterpret_cast<const float4*>(g_c + base);
    float c[4] = { c4.x, c4.y, c4.z, c4.w };

    float wk[8][4];
#pragma unroll
    for (int k = 0; k < 8; k++) {
        float4 t = *reinterpret_cast<const float4*>(g_w + k * BHW + base);
        wk[k][0] = t.x; wk[k][1] = t.y; wk[k][2] = t.z; wk[k][3] = t.w;
    }

    float o[4];
#pragma unroll
    for (int p = 0; p < 4; p++) {
        float acc = c[p];
        acc = fmaf(wk[0][p], rd[p + 2], acc);   // (+1,+1)
        acc = fmaf(wk[1][p], rd[p + 1], acc);   // (+1, 0)
        acc = fmaf(wk[2][p], rd[p],     acc);   // (+1,-1)
        acc = fmaf(wk[3][p], rm[p + 2], acc);   // ( 0,+1)
        acc = fmaf(wk[4][p], rm[p],     acc);   // ( 0,-1)
        acc = fmaf(wk[5][p], ru[p + 2], acc);   // (-1,+1)
        acc = fmaf(wk[6][p], ru[p + 1], acc);   // (-1, 0)
        acc = fmaf(wk[7][p], ru[p],     acc);   // (-1,-1)
        o[p] = acc;
    }
    *reinterpret_cast<float4*>(dst + base) = make_float4(o[0], o[1], o[2], o[3]);
}

extern "C" void kernel_launch(void* const* d_in, const int* in_sizes, int n_in,
                              void* d_out, int out_size) {
    const float* guid   = (const float*)d_in[0];   // (B, 8, H, W)
    const float* blur   = (const float*)d_in[1];   // (B, 1, H, W)
    const float* sparse = (const float*)d_in[2];   // (B, 1, H, W)
    float* out = (float*)d_out;                    // (B, H, W)

    const int PROP_TIME = 24;                      // fixed by setup_inputs

    prep_kernel<<<(BHW + 255) / 256, 256>>>(guid, blur, sparse);

    float* dbuf[2];
    cudaGetSymbolAddress((void**)&dbuf[0], g_d0);
    cudaGetSymbolAddress((void**)&dbuf[1], g_d1);

    dim3 block(32, 8, 1);
    dim3 grid(W / (32 * 4), H / 8, Bn);            // (10, 48, 2)

    const float* src = blur;
    for (int t = 1; t <= PROP_TIME; t++) {
        float* dst = (t == PROP_TIME) ? out : dbuf[t & 1];
        prop_kernel<<<grid, block>>>(src, dst);
        src = dst;
    }
}